// round 5
// baseline (speedup 1.0000x reference)
#include <cuda_runtime.h>
#include <cstdint>

// ThresholdDecision: per row b, output 1.0f iff the indicator stream
// (x[b,l,2] > 0.5) contains a run of 4 consecutive ones ending at l in
// [4, L-2]. (Matches reference: diffs_j = seqs[j+1..j+4], j in [0, L-CP-2].)
//
// KEY FIX (R3 finding): the harness checker reads d_out as FLOAT32 — integer
// bit patterns (1, 4444, 5555) all read as denormals ~ 0.0, producing the
// exact rel_err = 1.0 seen in rounds 1-3. Write real floats.
//
// One warp per row; ballot -> 64-bit shifted-AND run detect; 3-bit carry via
// previous ballot's top bits; warp-uniform early exit (ballot is uniform).

#define B_ROWS 4096
#define L_LEN  4096
#define THRESH 0.5f

#define WARPS_PER_BLOCK 8
#define THREADS (WARPS_PER_BLOCK * 32)
#define NBLOCKS (B_ROWS / WARPS_PER_BLOCK)     // 512
#define NCHUNK  (L_LEN / 32)                   // 128

__global__ void threshold_decision_kernel(const float* __restrict__ x,
                                          float* __restrict__ out,
                                          int size_ok) {
    const int row_id = blockIdx.x * WARPS_PER_BLOCK + (threadIdx.x >> 5);
    const int lane   = threadIdx.x & 31;
    const float* row = x + (size_t)row_id * (size_t)(L_LEN * 3);

    unsigned carry = 0;   // indicator bits for positions base-3..base-1
    float result = 0.0f;

    for (int c = 0; c < NCHUNK; ++c) {
        const int base = c * 32;

        const float v = row[(base + lane) * 3 + 2];
        const unsigned m = __ballot_sync(0xffffffffu, v > THRESH);

        // m64 bit j corresponds to position base + j - 3
        const uint64_t m64 = ((uint64_t)m << 3) | (uint64_t)carry;
        carry = m >> 29;   // positions base+29..31 feed the next chunk

        const uint64_t r = m64 & (m64 >> 1) & (m64 >> 2) & (m64 >> 3);
        unsigned e = (unsigned)r;              // bit k: 4-run ends at base+k

        if (c == 0)          e &= 0xFFFFFFF0u; // require run end >= 4
        if (c == NCHUNK - 1) e &= 0x7FFFFFFFu; // require run end <= L-2 (4094)

        if (e) { result = 1.0f; break; }       // uniform across the warp
    }

    if (lane == 0) {
        if (!size_ok) result = 4444.0f;        // diagnostic: bad n_in/in_sizes
        out[row_id] = result;
    }
}

extern "C" void kernel_launch(void* const* d_in, const int* in_sizes, int n_in,
                              void* d_out, int out_size) {
    const float* x = (const float*)d_in[0];
    float* out = (float*)d_out;
    const long long expect = (long long)B_ROWS * L_LEN * 3;
    const int size_ok = (n_in >= 1) && ((long long)in_sizes[0] == expect) &&
                        (out_size == B_ROWS);
    threshold_decision_kernel<<<NBLOCKS, THREADS>>>(x, out, size_ok);
}